// round 16
// baseline (speedup 1.0000x reference)
#include <cuda_runtime.h>
#include <cuda_fp16.h>
#include <cstdint>

// Problem constants
#define N_IMG 256   // B*T = 32*8
#define C_IN  128
#define K_OUT 128
#define HH    32
#define WW    32
#define NP    34    // padded H/W

// GEMM staging
#define STAGES  18                  // 9 taps x 2 c-halves (64 c each)
#define TILE_B  16384               // one 128x64 fp16 tile (128 rows x 128B)
#define BUF_B   (4 * TILE_B)        // 2 W limbs + 2 x limbs = 64 KiB
#define NBUF    3                   // 3-deep cp.async ring
#define SM_BUF0 1024                // bias in [0,512)
#define SM_TOTAL (SM_BUF0 + NBUF * BUF_B)   // 197,632 B

// ---------------- device scratch (static allocation, allowed) ----------------
#define LSTR ((size_t)N_IMG * NP * NP * C_IN)
__device__ __align__(256) __half g_x0[LSTR];
__device__ __align__(256) __half g_x1[LSTR];
#define WSTR (9 * 128 * 128)
__device__ __align__(256) __half g_w0[WSTR];
__device__ __align__(256) __half g_w1[WSTR];
__device__ float g_y[(size_t)N_IMG * K_OUT * HH * WW];   // conv output, 128 MiB

// ---------------- PTX helpers ----------------
__device__ __forceinline__ uint32_t smem_u32(const void* p) {
    uint32_t a;
    asm("{ .reg .u64 t; cvta.to.shared.u64 t, %1; cvt.u32.u64 %0, t; }"
        : "=r"(a) : "l"(p));
    return a;
}
__device__ __forceinline__ void cp16(uint32_t dst, const void* src) {
    asm volatile("cp.async.cg.shared.global [%0], [%1], 16;"
                 :: "r"(dst), "l"(src) : "memory");
}
#define CP_COMMIT() asm volatile("cp.async.commit_group;" ::: "memory")
#define CP_WAIT0()  asm volatile("cp.async.wait_group 0;" ::: "memory")
#define CP_WAIT1()  asm volatile("cp.async.wait_group 1;" ::: "memory")

__device__ __forceinline__ uint32_t swz(uint32_t off) {   // SW128 swizzle
    return off ^ ((off >> 3) & 0x70);
}

#define LDSM4(R, addr) \
    asm volatile("ldmatrix.sync.aligned.m8n8.x4.shared.b16 {%0,%1,%2,%3}, [%4];" \
        : "=r"((R)[0]), "=r"((R)[1]), "=r"((R)[2]), "=r"((R)[3]) : "r"(addr))

__device__ __forceinline__ void mma_f16(float* d, const uint32_t* a,
                                        const uint32_t* b) {
    asm volatile(
        "mma.sync.aligned.m16n8k16.row.col.f32.f16.f16.f32 "
        "{%0,%1,%2,%3}, {%4,%5,%6,%7}, {%8,%9}, {%0,%1,%2,%3};"
        : "+f"(d[0]), "+f"(d[1]), "+f"(d[2]), "+f"(d[3])
        : "r"(a[0]), "r"(a[1]), "r"(a[2]), "r"(a[3]), "r"(b[0]), "r"(b[1]));
}

// Zero-C variant: D = A*B + 0 — writes the accumulator fresh, replacing
// explicit register zeroing (saves 64 MOVs per warp per use site).
__device__ __forceinline__ void mma_f16_z(float* d, const uint32_t* a,
                                          const uint32_t* b) {
    asm volatile(
        "mma.sync.aligned.m16n8k16.row.col.f32.f16.f16.f32 "
        "{%0,%1,%2,%3}, {%4,%5,%6,%7}, {%8,%9}, {%10,%11,%12,%13};"
        : "=f"(d[0]), "=f"(d[1]), "=f"(d[2]), "=f"(d[3])
        : "r"(a[0]), "r"(a[1]), "r"(a[2]), "r"(a[3]), "r"(b[0]), "r"(b[1]),
          "f"(0.f), "f"(0.f), "f"(0.f), "f"(0.f));
}

__device__ __forceinline__ uint32_t pack_h2(__half a, __half b) {
    return (uint32_t)__half_as_ushort(a) | ((uint32_t)__half_as_ushort(b) << 16);
}

// ---------------------------------------------------------------------------
// Kernel A: zero-pad + transpose + fp16 2-limb split of x.
// x[n][c][h][w] fp32  ->  g_x{0,1}[n][hp][wp][c] fp16, hp/wp in [0,34).
// 4 channels per thread -> 64-bit (uint2) stores.
// ---------------------------------------------------------------------------
__global__ void pad_split_kernel(const float* __restrict__ x)
{
    __shared__ float ts[C_IN][WW + 1];
    const int n  = blockIdx.x;
    const int hp = blockIdx.y;
    const int tid = threadIdx.x;
    const size_t obase4 = ((size_t)(n * NP + hp)) * NP * (C_IN / 4); // uint2 units

    uint2* o0 = (uint2*)g_x0;
    uint2* o1 = (uint2*)g_x1;

    if (hp == 0 || hp == NP - 1) {
        const uint2 z = make_uint2(0u, 0u);
        for (int i = tid; i < NP * (C_IN / 4); i += 256) {
            o0[obase4 + i] = z; o1[obase4 + i] = z;
        }
        return;
    }
    const int h = hp - 1;
    for (int i = tid; i < C_IN * WW; i += 256) {
        int c = i >> 5, w = i & 31;
        ts[c][w] = x[((size_t)(n * C_IN + c) * HH + h) * WW + w];
    }
    __syncthreads();
    for (int i = tid; i < NP * (C_IN / 4); i += 256) {
        int wp = i >> 5, c4 = (i & 31) * 4;
        float v[4] = {0.f, 0.f, 0.f, 0.f};
        if (wp != 0 && wp != NP - 1) {
#pragma unroll
            for (int j = 0; j < 4; j++) v[j] = ts[c4 + j][wp - 1];
        }
        __half l0[4], l1[4];
#pragma unroll
        for (int j = 0; j < 4; j++) {
            l0[j] = __float2half_rn(v[j]);
            l1[j] = __float2half_rn(v[j] - __half2float(l0[j]));
        }
        o0[obase4 + i] = make_uint2(pack_h2(l0[0], l0[1]), pack_h2(l0[2], l0[3]));
        o1[obase4 + i] = make_uint2(pack_h2(l1[0], l1[1]), pack_h2(l1[2], l1[3]));
    }
}

// ---------------------------------------------------------------------------
// Kernel B: weight 2-limb split + relayout. W[k][c][3][3] fp32 ->
// g_w{0,1}[tap][k][c] fp16 (tap = r*3+s).
// ---------------------------------------------------------------------------
__global__ void wsplit_kernel(const float* __restrict__ W)
{
    int idx = blockIdx.x * blockDim.x + threadIdx.x;
    if (idx >= WSTR) return;
    int tap = idx / (128 * 128);
    int k   = (idx / 128) % 128;
    int c   = idx % 128;
    float v = W[((size_t)(k * 128 + c)) * 9 + tap];
    __half h0 = __float2half_rn(v);
    __half h1 = __float2half_rn(v - __half2float(h0));
    g_w0[idx] = h0;
    g_w1[idx] = h1;
}

// ---------------------------------------------------------------------------
// Kernel C: implicit-GEMM conv via warp-level fp16 mma.sync, 2-limb fp32
// emulation, 3-accumulator scheme with zero-C MMA resets:
//   workM: main h0g0; written fresh at ks=0 via zero-C MMA (no MOV zeroing),
//          per-stage HW chain = 4 full-magnitude adds; RN-folded into mast
//          every stage.
//   workC: corrections (h1g0, h0g1); accumulated over 6-stage windows
//          (48-add chains at magnitude ~1e-4 -> RZ bias negligible);
//          RN-folded into mast at stages 5/11/end; reset via zero-C MMA at
//          stages 0/6/12. Restores the rel_err margin R15 spent.
// CTA = 256 thr = 8 warps (2 M x 4 N); CTA tile M=128 k, N=128 px;
// warp tile 64x32; 3-deep cp.async ring. MMA count unchanged from R15.
// ---------------------------------------------------------------------------
__device__ __forceinline__ void stage_load(uint32_t smb, int buf, int s,
                                           int n, int hb)
{
    const int tap = s >> 1, ch = s & 1;
    const int r = tap / 3, sc = tap % 3, c0 = ch * 64;
    const uint32_t base = smb + SM_BUF0 + buf * BUF_B;
    const int tid = threadIdx.x;
    const __half* wl[2] = { g_w0, g_w1 };
    const __half* xl[2] = { g_x0, g_x1 };

    // W tiles (operand A): 128 k-rows x 64 c (128B rows), 2 limbs
    for (int q = tid; q < 2048; q += 256) {
        int l = q >> 10, rem = q & 1023, k = rem >> 3, seg = rem & 7;
        const void* src = wl[l] + (size_t)(tap * 128 + k) * 128 + c0 + seg * 8;
        cp16(base + l * TILE_B + swz(k * 128 + seg * 16), src);
    }
    // x tiles (operand B): 128 px-rows x 64 c, 2 limbs
    for (int q = tid; q < 2048; q += 256) {
        int l = q >> 10, rem = q & 1023, p = rem >> 3, seg = rem & 7;
        int hrow = hb * 4 + (p >> 5) + r;
        int wcol = (p & 31) + sc;
        const void* src = xl[l] +
            ((size_t)(n * NP + hrow) * NP + wcol) * C_IN + c0 + seg * 8;
        cp16(base + (2 + l) * TILE_B + swz(p * 128 + seg * 16), src);
    }
}

__global__ __launch_bounds__(256, 1)
void conv_mma_kernel(const float* __restrict__ bias)
{
    extern __shared__ char sm[];
    const uint32_t smb = smem_u32(sm);
    const int tid = threadIdx.x, wid = tid >> 5, lane = tid & 31;
    const int n = blockIdx.x, hb = blockIdx.y;

    if (tid < 128) ((float*)sm)[tid] = bias[tid];

    const int wm = (wid >> 2) * 64;   // k offset of warp tile
    const int wn = (wid & 3) * 32;    // px offset of warp tile

    float mast[4][4][4], workC[4][4][4], workM[4][4][4];
#pragma unroll
    for (int mt = 0; mt < 4; mt++)
#pragma unroll
        for (int nt = 0; nt < 4; nt++)
#pragma unroll
            for (int j = 0; j < 4; j++) {
                mast[mt][nt][j] = 0.f; workC[mt][nt][j] = 0.f; workM[mt][nt][j] = 0.f;
            }

    // Prologue: stages 0 and 1 in flight
    stage_load(smb, 0, 0, n, hb);
    CP_COMMIT();
    stage_load(smb, 1, 1, n, hb);
    CP_COMMIT();

    // Lane-constant address components
    const uint32_t arow = (lane & 15);
    const uint32_t acol = (lane >> 4) * 16;
    const uint32_t brow = (lane & 7) + (lane >> 4) * 8;
    const uint32_t bcol = ((lane >> 3) & 1) * 16;

    int cur = 0, nxt2 = 2;                 // buf of stage s, buf of stage s+2
#pragma unroll 1
    for (int s = 0; s < STAGES; s++) {
        if (s + 1 < STAGES) { CP_WAIT1(); } else { CP_WAIT0(); }
        __syncthreads();                 // stage s visible; buf nxt2 free
        if (s + 2 < STAGES) {
            stage_load(smb, nxt2, s + 2, n, hb);
            CP_COMMIT();
        }

        const uint32_t abase = smb + SM_BUF0 + cur * BUF_B;
        const uint32_t bbase = abase + 2 * TILE_B;
        const bool rstC = (s == 0) || (s == 6) || (s == 12);  // workC reset stages

        uint32_t A[4][4], B[2][4];

#define LOAD_A(limb, ks)                                                     \
        {                                                                    \
            _Pragma("unroll")                                                \
            for (int mt = 0; mt < 4; mt++)                                   \
                LDSM4(A[mt], abase + (limb) * TILE_B +                       \
                      swz((wm + mt * 16 + arow) * 128 + (ks) * 32 + acol));  \
        }
#define LOAD_B(limb, ks)                                                     \
        {                                                                    \
            _Pragma("unroll")                                                \
            for (int ntp = 0; ntp < 2; ntp++)                                \
                LDSM4(B[ntp], bbase + (limb) * TILE_B +                      \
                      swz((wn + ntp * 16 + brow) * 128 + (ks) * 32 + bcol)); \
        }
#define MMA_ALL(dst)                                                         \
        {                                                                    \
            _Pragma("unroll")                                                \
            for (int mt = 0; mt < 4; mt++)                                   \
                _Pragma("unroll")                                            \
                for (int nt = 0; nt < 4; nt++)                               \
                    mma_f16((dst)[mt][nt], A[mt], &B[nt >> 1][(nt & 1) * 2]);\
        }
#define MMA_ALL_Z(dst)                                                       \
        {                                                                    \
            _Pragma("unroll")                                                \
            for (int mt = 0; mt < 4; mt++)                                   \
                _Pragma("unroll")                                            \
                for (int nt = 0; nt < 4; nt++)                               \
                    mma_f16_z((dst)[mt][nt], A[mt], &B[nt >> 1][(nt & 1) * 2]);\
        }

        // ---- ks = 0: zero-C resets (workM every stage; workC at reset stages)
        {
            LOAD_B(1, 0);
            LOAD_A(0, 0);
            if (rstC) { MMA_ALL_Z(workC); } else { MMA_ALL(workC); }   // h0*g1
            LOAD_B(0, 0);
            MMA_ALL_Z(workM);                                          // h0*g0
            LOAD_A(1, 0);
            MMA_ALL(workC);                                            // h1*g0
        }
        // ---- ks = 1..3: plain accumulation
#pragma unroll
        for (int ks = 1; ks < 4; ks++) {
            LOAD_B(1, ks);
            LOAD_A(0, ks);
            MMA_ALL(workC);                // h0*g1
            LOAD_B(0, ks);
            MMA_ALL(workM);                // h0*g0
            LOAD_A(1, ks);
            MMA_ALL(workC);                // h1*g0
        }
#undef LOAD_A
#undef LOAD_B
#undef MMA_ALL
#undef MMA_ALL_Z

        // ---- Fold main working -> master in RN every stage (no re-zero) ----
#pragma unroll
        for (int mt = 0; mt < 4; mt++)
#pragma unroll
            for (int nt = 0; nt < 4; nt++)
#pragma unroll
                for (int j = 0; j < 4; j++)
                    mast[mt][nt][j] += workM[mt][nt][j];

        // ---- Fold corrections at window boundaries (stages 5, 11) ----
        if (s == 5 || s == 11) {
#pragma unroll
            for (int mt = 0; mt < 4; mt++)
#pragma unroll
                for (int nt = 0; nt < 4; nt++)
#pragma unroll
                    for (int j = 0; j < 4; j++)
                        mast[mt][nt][j] += workC[mt][nt][j];
        }

        cur  = (cur == NBUF - 1) ? 0 : cur + 1;
        nxt2 = (nxt2 == NBUF - 1) ? 0 : nxt2 + 1;
    }

    // Final fold: last correction window (stages 12..17) -> master, RN
#pragma unroll
    for (int mt = 0; mt < 4; mt++)
#pragma unroll
        for (int nt = 0; nt < 4; nt++)
#pragma unroll
            for (int j = 0; j < 4; j++)
                mast[mt][nt][j] += workC[mt][nt][j];

    // Epilogue: acc(k, px) + bias[k] -> g_y[n][k][hb*128 + px], float2 stores
#pragma unroll
    for (int mt = 0; mt < 4; mt++) {
        const int k0 = wm + mt * 16 + (lane >> 2);
        const float bv0 = ((const float*)sm)[k0];
        const float bv1 = ((const float*)sm)[k0 + 8];
#pragma unroll
        for (int nt = 0; nt < 4; nt++) {
            const int px = wn + nt * 8 + (lane & 3) * 2;
            size_t g0 = ((size_t)(n * K_OUT + k0)) * (HH * WW) + hb * 128 + px;
            float2 v0 = make_float2(mast[mt][nt][0] + bv0, mast[mt][nt][1] + bv0);
            float2 v1 = make_float2(mast[mt][nt][2] + bv1, mast[mt][nt][3] + bv1);
            *(float2*)(g_y + g0) = v0;
            *(float2*)(g_y + g0 + 8 * (size_t)(HH * WW)) = v1;
        }
    }
}

// ---------------------------------------------------------------------------
// Kernel D: spiking scan over T=8. All 8 timestep loads prefetched into
// registers (MLP=8); arithmetic order unchanged.
// ---------------------------------------------------------------------------
__global__ void spike_scan_kernel(const float* __restrict__ thr_p,
                                  float* __restrict__ out)
{
    const int PER_B4 = (C_IN * HH * WW) / 4;   // 32768 float4 groups per batch
    int idx = blockIdx.x * blockDim.x + threadIdx.x;
    if (idx >= 32 * PER_B4) return;

    const float thr = thr_p[0];
    int b = idx >> 15;
    int g = idx & 32767;

    const float4* y4 = (const float4*)g_y;
    float4*       o4 = (float4*)out;
    size_t base = (size_t)(b * 8) * PER_B4 + g;

    float4 v[8];
#pragma unroll
    for (int t = 0; t < 8; t++) v[t] = y4[base + (size_t)t * PER_B4];

    float mem[4], sum[4];
#pragma unroll
    for (int j = 0; j < 4; j++) { mem[j] = 0.5f * thr; sum[j] = 0.f; }

#pragma unroll
    for (int t = 0; t < 8; t++) {
        float xin[4] = {v[t].x, v[t].y, v[t].z, v[t].w};
        float o[4];
#pragma unroll
        for (int j = 0; j < 4; j++) {
            mem[j] += xin[j];
            float sp = (mem[j] >= thr) ? 1.f : 0.f;
            mem[j] -= thr * sp;
            sum[j] += sp;
            float inh = ((mem[j] <= -0.001f) && (sum[j] > 0.f)) ? 1.f : 0.f;
            mem[j] += thr * inh;
            sum[j] -= inh;
            o[j] = (sp - inh) * thr;
        }
        o4[base + (size_t)t * PER_B4] = make_float4(o[0], o[1], o[2], o[3]);
    }
}

// ---------------------------------------------------------------------------
extern "C" void kernel_launch(void* const* d_in, const int* in_sizes, int n_in,
                              void* d_out, int out_size)
{
    const float* x    = (const float*)d_in[0];
    const float* W    = (const float*)d_in[1];
    const float* bias = (const float*)d_in[2];
    const float* thr  = (const float*)d_in[3];
    float* out        = (float*)d_out;

    cudaFuncSetAttribute(conv_mma_kernel,
                         cudaFuncAttributeMaxDynamicSharedMemorySize, SM_TOTAL);

    pad_split_kernel<<<dim3(N_IMG, NP), 256>>>(x);
    wsplit_kernel<<<(WSTR + 255) / 256, 256>>>(W);
    conv_mma_kernel<<<dim3(N_IMG, 8), 256, SM_TOTAL>>>(bias);

    int groups = 32 * (C_IN * HH * WW) / 4;
    spike_scan_kernel<<<groups / 256, 256>>>(thr, out);
}

// round 17
// speedup vs baseline: 1.0132x; 1.0132x over previous
#include <cuda_runtime.h>
#include <cuda_fp16.h>
#include <cstdint>

// Problem constants
#define N_IMG 256   // B*T = 32*8
#define C_IN  128
#define K_OUT 128
#define HH    32
#define WW    32
#define NP    34    // padded H/W

// GEMM staging
#define STAGES  18                  // 9 taps x 2 c-halves (64 c each)
#define TILE_B  16384               // one 128x64 fp16 tile (128 rows x 128B)
#define BUF_B   (4 * TILE_B)        // 2 W limbs + 2 x limbs = 64 KiB
#define NBUF    3                   // 3-deep cp.async ring
#define SM_BUF0 1024                // bias in [0,512)
#define SM_TOTAL (SM_BUF0 + NBUF * BUF_B)   // 197,632 B

// ---------------- device scratch (static allocation, allowed) ----------------
#define LSTR ((size_t)N_IMG * NP * NP * C_IN)
__device__ __align__(256) __half g_x0[LSTR];
__device__ __align__(256) __half g_x1[LSTR];
#define WSTR (9 * 128 * 128)
__device__ __align__(256) __half g_w0[WSTR];
__device__ __align__(256) __half g_w1[WSTR];
__device__ float g_y[(size_t)N_IMG * K_OUT * HH * WW];   // conv output, 128 MiB

// ---------------- PTX helpers ----------------
__device__ __forceinline__ uint32_t smem_u32(const void* p) {
    uint32_t a;
    asm("{ .reg .u64 t; cvta.to.shared.u64 t, %1; cvt.u32.u64 %0, t; }"
        : "=r"(a) : "l"(p));
    return a;
}
__device__ __forceinline__ void cp16(uint32_t dst, const void* src) {
    asm volatile("cp.async.cg.shared.global [%0], [%1], 16;"
                 :: "r"(dst), "l"(src) : "memory");
}
#define CP_COMMIT() asm volatile("cp.async.commit_group;" ::: "memory")
#define CP_WAIT0()  asm volatile("cp.async.wait_group 0;" ::: "memory")
#define CP_WAIT1()  asm volatile("cp.async.wait_group 1;" ::: "memory")

__device__ __forceinline__ uint32_t swz(uint32_t off) {   // SW128 swizzle
    return off ^ ((off >> 3) & 0x70);
}

#define LDSM4(R, addr) \
    asm volatile("ldmatrix.sync.aligned.m8n8.x4.shared.b16 {%0,%1,%2,%3}, [%4];" \
        : "=r"((R)[0]), "=r"((R)[1]), "=r"((R)[2]), "=r"((R)[3]) : "r"(addr))

__device__ __forceinline__ void mma_f16(float* d, const uint32_t* a,
                                        const uint32_t* b) {
    asm volatile(
        "mma.sync.aligned.m16n8k16.row.col.f32.f16.f16.f32 "
        "{%0,%1,%2,%3}, {%4,%5,%6,%7}, {%8,%9}, {%0,%1,%2,%3};"
        : "+f"(d[0]), "+f"(d[1]), "+f"(d[2]), "+f"(d[3])
        : "r"(a[0]), "r"(a[1]), "r"(a[2]), "r"(a[3]), "r"(b[0]), "r"(b[1]));
}

__device__ __forceinline__ uint32_t pack_h2(__half a, __half b) {
    return (uint32_t)__half_as_ushort(a) | ((uint32_t)__half_as_ushort(b) << 16);
}

// ---------------------------------------------------------------------------
// Kernel A: zero-pad + transpose + fp16 2-limb split of x.
// x[n][c][h][w] fp32  ->  g_x{0,1}[n][hp][wp][c] fp16, hp/wp in [0,34).
// 4 channels per thread -> 64-bit (uint2) stores. (DRAM-bound; at floor.)
// ---------------------------------------------------------------------------
__global__ void pad_split_kernel(const float* __restrict__ x)
{
    __shared__ float ts[C_IN][WW + 1];
    const int n  = blockIdx.x;
    const int hp = blockIdx.y;
    const int tid = threadIdx.x;
    const size_t obase4 = ((size_t)(n * NP + hp)) * NP * (C_IN / 4); // uint2 units

    uint2* o0 = (uint2*)g_x0;
    uint2* o1 = (uint2*)g_x1;

    if (hp == 0 || hp == NP - 1) {
        const uint2 z = make_uint2(0u, 0u);
        for (int i = tid; i < NP * (C_IN / 4); i += 256) {
            o0[obase4 + i] = z; o1[obase4 + i] = z;
        }
        return;
    }
    const int h = hp - 1;
    for (int i = tid; i < C_IN * WW; i += 256) {
        int c = i >> 5, w = i & 31;
        ts[c][w] = x[((size_t)(n * C_IN + c) * HH + h) * WW + w];
    }
    __syncthreads();
    for (int i = tid; i < NP * (C_IN / 4); i += 256) {
        int wp = i >> 5, c4 = (i & 31) * 4;
        float v[4] = {0.f, 0.f, 0.f, 0.f};
        if (wp != 0 && wp != NP - 1) {
#pragma unroll
            for (int j = 0; j < 4; j++) v[j] = ts[c4 + j][wp - 1];
        }
        __half l0[4], l1[4];
#pragma unroll
        for (int j = 0; j < 4; j++) {
            l0[j] = __float2half_rn(v[j]);
            l1[j] = __float2half_rn(v[j] - __half2float(l0[j]));
        }
        o0[obase4 + i] = make_uint2(pack_h2(l0[0], l0[1]), pack_h2(l0[2], l0[3]));
        o1[obase4 + i] = make_uint2(pack_h2(l1[0], l1[1]), pack_h2(l1[2], l1[3]));
    }
}

// ---------------------------------------------------------------------------
// Kernel B: weight 2-limb split + relayout. W[k][c][3][3] fp32 ->
// g_w{0,1}[tap][k][c] fp16 (tap = r*3+s).
// ---------------------------------------------------------------------------
__global__ void wsplit_kernel(const float* __restrict__ W)
{
    int idx = blockIdx.x * blockDim.x + threadIdx.x;
    if (idx >= WSTR) return;
    int tap = idx / (128 * 128);
    int k   = (idx / 128) % 128;
    int c   = idx % 128;
    float v = W[((size_t)(k * 128 + c)) * 9 + tap];
    __half h0 = __float2half_rn(v);
    __half h1 = __float2half_rn(v - __half2float(h0));
    g_w0[idx] = h0;
    g_w1[idx] = h1;
}

// ---------------------------------------------------------------------------
// Kernel C: implicit-GEMM conv via warp-level fp16 mma.sync, 2-limb fp32
// emulation, 3-accumulator scheme (R15 arithmetic, verbatim):
//   workC: corrections (h1g0, h0g1), accumulated whole-kernel at ~1e-4
//          magnitude (RZ bias negligible), one RN fold at the end.
//   workM: main h0g0, 4 full-magnitude HW adds per stage, RN-folded into
//          mast every stage.
// R17 change: stage_load(s+2) issues AFTER the stage's MMAs+fold instead of
// before them, so the tensor pipe refills immediately after the barrier
// instead of waiting out ~150 cyc of cp.async/address-ALU issue. NBUF=3
// leaves >1 full stage-time of prefetch slack, so the fetch stays covered.
// ---------------------------------------------------------------------------
__device__ __forceinline__ void stage_load(uint32_t smb, int buf, int s,
                                           int n, int hb)
{
    const int tap = s >> 1, ch = s & 1;
    const int r = tap / 3, sc = tap % 3, c0 = ch * 64;
    const uint32_t base = smb + SM_BUF0 + buf * BUF_B;
    const int tid = threadIdx.x;
    const __half* wl[2] = { g_w0, g_w1 };
    const __half* xl[2] = { g_x0, g_x1 };

    // W tiles (operand A): 128 k-rows x 64 c (128B rows), 2 limbs
    for (int q = tid; q < 2048; q += 256) {
        int l = q >> 10, rem = q & 1023, k = rem >> 3, seg = rem & 7;
        const void* src = wl[l] + (size_t)(tap * 128 + k) * 128 + c0 + seg * 8;
        cp16(base + l * TILE_B + swz(k * 128 + seg * 16), src);
    }
    // x tiles (operand B): 128 px-rows x 64 c, 2 limbs
    for (int q = tid; q < 2048; q += 256) {
        int l = q >> 10, rem = q & 1023, p = rem >> 3, seg = rem & 7;
        int hrow = hb * 4 + (p >> 5) + r;
        int wcol = (p & 31) + sc;
        const void* src = xl[l] +
            ((size_t)(n * NP + hrow) * NP + wcol) * C_IN + c0 + seg * 8;
        cp16(base + (2 + l) * TILE_B + swz(p * 128 + seg * 16), src);
    }
}

__global__ __launch_bounds__(256, 1)
void conv_mma_kernel(const float* __restrict__ bias)
{
    extern __shared__ char sm[];
    const uint32_t smb = smem_u32(sm);
    const int tid = threadIdx.x, wid = tid >> 5, lane = tid & 31;
    const int n = blockIdx.x, hb = blockIdx.y;

    if (tid < 128) ((float*)sm)[tid] = bias[tid];

    const int wm = (wid >> 2) * 64;   // k offset of warp tile
    const int wn = (wid & 3) * 32;    // px offset of warp tile

    float mast[4][4][4], workC[4][4][4], workM[4][4][4];
#pragma unroll
    for (int mt = 0; mt < 4; mt++)
#pragma unroll
        for (int nt = 0; nt < 4; nt++)
#pragma unroll
            for (int j = 0; j < 4; j++) {
                mast[mt][nt][j] = 0.f; workC[mt][nt][j] = 0.f; workM[mt][nt][j] = 0.f;
            }

    // Prologue: stages 0 and 1 in flight
    stage_load(smb, 0, 0, n, hb);
    CP_COMMIT();
    stage_load(smb, 1, 1, n, hb);
    CP_COMMIT();

    // Lane-constant address components
    const uint32_t arow = (lane & 15);
    const uint32_t acol = (lane >> 4) * 16;
    const uint32_t brow = (lane & 7) + (lane >> 4) * 8;
    const uint32_t bcol = ((lane >> 3) & 1) * 16;

    int cur = 0, nxt2 = 2;                 // buf of stage s, buf of stage s+2
#pragma unroll 1
    for (int s = 0; s < STAGES; s++) {
        if (s + 1 < STAGES) { CP_WAIT1(); } else { CP_WAIT0(); }
        __syncthreads();                 // stage s visible; buf nxt2 free

        const uint32_t abase = smb + SM_BUF0 + cur * BUF_B;
        const uint32_t bbase = abase + 2 * TILE_B;

        uint32_t A[4][4], B[2][4];

#define LOAD_A(limb, ks)                                                     \
        {                                                                    \
            _Pragma("unroll")                                                \
            for (int mt = 0; mt < 4; mt++)                                   \
                LDSM4(A[mt], abase + (limb) * TILE_B +                       \
                      swz((wm + mt * 16 + arow) * 128 + (ks) * 32 + acol));  \
        }
#define LOAD_B(limb, ks)                                                     \
        {                                                                    \
            _Pragma("unroll")                                                \
            for (int ntp = 0; ntp < 2; ntp++)                                \
                LDSM4(B[ntp], bbase + (limb) * TILE_B +                      \
                      swz((wn + ntp * 16 + brow) * 128 + (ks) * 32 + bcol)); \
        }
#define MMA_ALL(dst)                                                         \
        {                                                                    \
            _Pragma("unroll")                                                \
            for (int mt = 0; mt < 4; mt++)                                   \
                _Pragma("unroll")                                            \
                for (int nt = 0; nt < 4; nt++)                               \
                    mma_f16((dst)[mt][nt], A[mt], &B[nt >> 1][(nt & 1) * 2]);\
        }

        // ---- MMAs first: tensor pipe refills immediately after the barrier.
        //      A0/B0 loaded once per ks; corrections -> workC, main -> workM.
#pragma unroll
        for (int ks = 0; ks < 4; ks++) {
            LOAD_B(1, ks);
            LOAD_A(0, ks);
            MMA_ALL(workC);                // h0*g1
            LOAD_B(0, ks);
            MMA_ALL(workM);                // h0*g0
            LOAD_A(1, ks);
            MMA_ALL(workC);                // h1*g0
        }
#undef LOAD_A
#undef LOAD_B
#undef MMA_ALL

        // ---- Fold main working -> master in RN every stage ----
#pragma unroll
        for (int mt = 0; mt < 4; mt++)
#pragma unroll
            for (int nt = 0; nt < 4; nt++)
#pragma unroll
                for (int j = 0; j < 4; j++) {
                    mast[mt][nt][j] += workM[mt][nt][j];
                    workM[mt][nt][j] = 0.f;
                }

        // ---- Prefetch stage s+2 LAST (issues under the MMA-drain shadow;
        //      NBUF=3 keeps the fetch covered by >1 full stage-time) ----
        if (s + 2 < STAGES) {
            stage_load(smb, nxt2, s + 2, n, hb);
            CP_COMMIT();
        }

        cur  = (cur == NBUF - 1) ? 0 : cur + 1;
        nxt2 = (nxt2 == NBUF - 1) ? 0 : nxt2 + 1;
    }

    // Final fold: corrections (accumulated at small magnitude) -> master, RN
#pragma unroll
    for (int mt = 0; mt < 4; mt++)
#pragma unroll
        for (int nt = 0; nt < 4; nt++)
#pragma unroll
            for (int j = 0; j < 4; j++)
                mast[mt][nt][j] += workC[mt][nt][j];

    // Epilogue: acc(k, px) + bias[k] -> g_y[n][k][hb*128 + px], float2 stores
#pragma unroll
    for (int mt = 0; mt < 4; mt++) {
        const int k0 = wm + mt * 16 + (lane >> 2);
        const float bv0 = ((const float*)sm)[k0];
        const float bv1 = ((const float*)sm)[k0 + 8];
#pragma unroll
        for (int nt = 0; nt < 4; nt++) {
            const int px = wn + nt * 8 + (lane & 3) * 2;
            size_t g0 = ((size_t)(n * K_OUT + k0)) * (HH * WW) + hb * 128 + px;
            float2 v0 = make_float2(mast[mt][nt][0] + bv0, mast[mt][nt][1] + bv0);
            float2 v1 = make_float2(mast[mt][nt][2] + bv1, mast[mt][nt][3] + bv1);
            *(float2*)(g_y + g0) = v0;
            *(float2*)(g_y + g0 + 8 * (size_t)(HH * WW)) = v1;
        }
    }
}

// ---------------------------------------------------------------------------
// Kernel D: spiking scan over T=8. All 8 timestep loads prefetched into
// registers (MLP=8); arithmetic order unchanged.
// ---------------------------------------------------------------------------
__global__ void spike_scan_kernel(const float* __restrict__ thr_p,
                                  float* __restrict__ out)
{
    const int PER_B4 = (C_IN * HH * WW) / 4;   // 32768 float4 groups per batch
    int idx = blockIdx.x * blockDim.x + threadIdx.x;
    if (idx >= 32 * PER_B4) return;

    const float thr = thr_p[0];
    int b = idx >> 15;
    int g = idx & 32767;

    const float4* y4 = (const float4*)g_y;
    float4*       o4 = (float4*)out;
    size_t base = (size_t)(b * 8) * PER_B4 + g;

    float4 v[8];
#pragma unroll
    for (int t = 0; t < 8; t++) v[t] = y4[base + (size_t)t * PER_B4];

    float mem[4], sum[4];
#pragma unroll
    for (int j = 0; j < 4; j++) { mem[j] = 0.5f * thr; sum[j] = 0.f; }

#pragma unroll
    for (int t = 0; t < 8; t++) {
        float xin[4] = {v[t].x, v[t].y, v[t].z, v[t].w};
        float o[4];
#pragma unroll
        for (int j = 0; j < 4; j++) {
            mem[j] += xin[j];
            float sp = (mem[j] >= thr) ? 1.f : 0.f;
            mem[j] -= thr * sp;
            sum[j] += sp;
            float inh = ((mem[j] <= -0.001f) && (sum[j] > 0.f)) ? 1.f : 0.f;
            mem[j] += thr * inh;
            sum[j] -= inh;
            o[j] = (sp - inh) * thr;
        }
        o4[base + (size_t)t * PER_B4] = make_float4(o[0], o[1], o[2], o[3]);
    }
}

// ---------------------------------------------------------------------------
extern "C" void kernel_launch(void* const* d_in, const int* in_sizes, int n_in,
                              void* d_out, int out_size)
{
    const float* x    = (const float*)d_in[0];
    const float* W    = (const float*)d_in[1];
    const float* bias = (const float*)d_in[2];
    const float* thr  = (const float*)d_in[3];
    float* out        = (float*)d_out;

    cudaFuncSetAttribute(conv_mma_kernel,
                         cudaFuncAttributeMaxDynamicSharedMemorySize, SM_TOTAL);

    pad_split_kernel<<<dim3(N_IMG, NP), 256>>>(x);
    wsplit_kernel<<<(WSTR + 255) / 256, 256>>>(W);
    conv_mma_kernel<<<dim3(N_IMG, 8), 256, SM_TOTAL>>>(bias);

    int groups = 32 * (C_IN * HH * WW) / 4;
    spike_scan_kernel<<<groups / 256, 256>>>(thr, out);
}